// round 15
// baseline (speedup 1.0000x reference)
#include <cuda_runtime.h>
#include <cstdint>

// VDEmbedding: out[t,:] = mask[x[t]] * weight[x[t],:], zero at pad (idx==0).
// x: [65536] int64 OR int32 (auto-detected), weight: [128000,128] f32,
// mask: [128000] f32, out: [65536,128] f32.
//
// R11: gathers via per-lane 16B cp.async.cg (SASS LDGSTS: no observed depth
// cap, L1-bypass L2->SMEM fill) instead of LDG (M_max ~55 / MSHR-capped).
// 8 tokens/warp in flight, commit_group/wait_group ordering only (each lane
// reads back exactly the bytes it copied -- no cross-thread visibility
// needed, no mbarriers, no phases). Front end is the proven R6 structure.

#define EMBED_V4 32     // 128 floats = 32 float4 per row
#define TOK      8      // tokens per warp
#define THREADS  128    // 4 warps per block
#define ROWB     512    // bytes per row

__device__ __forceinline__ uint32_t smem_u32(const void* p) {
    uint32_t a;
    asm("{ .reg .u64 t; cvta.to.shared.u64 t, %1; cvt.u32.u64 %0, t; }"
        : "=r"(a) : "l"(p));
    return a;
}

__global__ __launch_bounds__(THREADS) void vdembed_kernel(
    const unsigned int* __restrict__ x32,   // raw index words (i32 or i64)
    const char*         __restrict__ wbytes,// weight table, 512B rows
    const float*        __restrict__ mask,
    float4*             __restrict__ out4,  // out as [T, 32] float4
    int n_tokens)
{
    __shared__ __align__(16) char s_rows[4][TOK * ROWB];   // 4KB per warp

    const int lane = threadIdx.x & 31;
    const int wid  = (threadIdx.x >> 5) & 3;
    const int warp = (int)((blockIdx.x * blockDim.x + threadIdx.x) >> 5);
    const int t0   = warp * TOK;
    if (t0 >= n_tokens) return;

    // ---- concurrent: dtype probe + speculative i32 index loads ----
    // int64 data => all odd 32-bit words zero; int32 => odd words are random
    // token ids (P(32 zeros) ~ (1/128000)^32 ~ 0). 256B, L1-broadcast-hot.
    // uint4 loads at word offsets t0..t0+7 are in-bounds for BOTH layouts.
    unsigned int probe = x32[2 * lane + 1];
    const uint4* xi = (const uint4*)x32;
    uint4 a32 = __ldg(&xi[(t0 >> 2) + 0]);
    uint4 b32 = __ldg(&xi[(t0 >> 2) + 1]);

    probe = __reduce_or_sync(0xffffffffu, probe);

    unsigned int id[TOK];
    if (probe == 0u) {   // int64 layout
        const ulonglong2* xl = (const ulonglong2*)x32;
#pragma unroll
        for (int p = 0; p < 4; p++) {
            ulonglong2 a = __ldg(&xl[(t0 >> 1) + p]);
            id[2 * p]     = (unsigned int)a.x;
            id[2 * p + 1] = (unsigned int)a.y;
        }
    } else {             // int32 layout
        id[0] = a32.x; id[1] = a32.y; id[2] = a32.z; id[3] = a32.w;
        id[4] = b32.x; id[5] = b32.y; id[6] = b32.z; id[7] = b32.w;
    }

    // ---- 8 row gathers via cp.async.cg: 16B per lane per token ----
    const uint32_t sbase = smem_u32(&s_rows[wid][0]) + (uint32_t)lane * 16u;
#pragma unroll
    for (int t = 0; t < TOK; t++) {
        const char* src = wbytes + (size_t)id[t] * ROWB + (size_t)lane * 16u;
        asm volatile("cp.async.cg.shared.global [%0], [%1], 16;"
                     :: "r"(sbase + (uint32_t)t * ROWB), "l"(src) : "memory");
    }
    asm volatile("cp.async.commit_group;" ::: "memory");

    // ---- scale loads overlap the in-flight LDGSTS ----
    float sc[TOK];
#pragma unroll
    for (int t = 0; t < TOK; t++)
        sc[t] = (id[t] == 0u) ? 0.0f : __ldg(&mask[id[t]]);

    asm volatile("cp.async.wait_group 0;" ::: "memory");

    // ---- read back own 16B, scale, streaming store ----
    float4* o = out4 + (size_t)t0 * EMBED_V4 + lane;
    if (t0 + TOK <= n_tokens) {
#pragma unroll
        for (int t = 0; t < TOK; t++) {
            float4 v = *(const float4*)(s_rows[wid] + t * ROWB + lane * 16);
            v.x *= sc[t]; v.y *= sc[t]; v.z *= sc[t]; v.w *= sc[t];
            __stcs(o + (size_t)t * EMBED_V4, v);
        }
    } else {
#pragma unroll
        for (int t = 0; t < TOK; t++) {
            if (t0 + t < n_tokens) {
                float4 v = *(const float4*)(s_rows[wid] + t * ROWB + lane * 16);
                v.x *= sc[t]; v.y *= sc[t]; v.z *= sc[t]; v.w *= sc[t];
                __stcs(o + (size_t)t * EMBED_V4, v);
            }
        }
    }
}

extern "C" void kernel_launch(void* const* d_in, const int* in_sizes, int n_in,
                              void* d_out, int out_size) {
    const unsigned int* x   = (const unsigned int*)d_in[0]; // [B*S] i64 or i32
    const char*         w   = (const char*)d_in[1];         // [V,128] f32 rows
    const float*        msk = (const float*)d_in[2];        // [V]
    float*              out = (float*)d_out;                // [B*S,128] f32

    const int n_tokens = in_sizes[0];
    const int warps    = (n_tokens + TOK - 1) / TOK;
    const int blocks   = (warps + 3) / 4;                   // 4 warps/block

    vdembed_kernel<<<blocks, THREADS>>>(
        x, w, msk, (float4*)out, n_tokens);
}

// round 16
// speedup vs baseline: 1.2149x; 1.2149x over previous
#include <cuda_runtime.h>

// VDEmbedding: out[t, :] = mask[x[t]] * weight[x[t], :], zero at pad (idx==0).
// x: [65536] int64 OR int32 (auto-detected), weight: [128000,128] f32,
// mask: [128000] f32, out: [65536,128] f32.
//
// R12: exact R6 winner (10.72us) with ONE change: row gathers use __ldcg
// (LDG.E.CG, L2-only) instead of __ldg. The 65.5MB table at random access
// has ~0.3% L1 hit rate -- L1 fills are pure pollution + fill-bandwidth
// waste (L1 was the busiest tier at 35%). Mask keeps __ldg (512KB, real
// partial L1 reuse). Single-variable A/B.

#define EMBED_V4 32     // 128 floats = 32 float4 per row
#define TOK_PER_WARP 4
#define THREADS 128

__global__ __launch_bounds__(THREADS) void vdembed_kernel(
    const unsigned int* __restrict__ x32,  // raw index words (i32 or i64 layout)
    const float4*       __restrict__ w4,   // weight as [V, 32] float4
    const float*        __restrict__ mask,
    float4*             __restrict__ out4, // out as [T, 32] float4
    int n_tokens)
{
    const int lane = threadIdx.x & 31;
    const int warp = (int)((blockIdx.x * blockDim.x + threadIdx.x) >> 5);
    const int t0   = warp * TOK_PER_WARP;
    if (t0 >= n_tokens) return;

    // ---- issue concurrently: dtype probe + speculative i32 index load ----
    // int64 data => all odd 32-bit words zero; int32 => odd words are random
    // token ids (P(32 zeros) ~ (1/128000)^32 ~ 0). 256B, L1-broadcast-hot.
    // The uint4 load at word offset t0 is in-bounds for BOTH layouts.
    unsigned int probe = x32[2 * lane + 1];
    const uint4* xi = (const uint4*)x32;
    uint4 a32 = __ldg(&xi[t0 >> 2]);               // speculative i32 indices

    probe = __reduce_or_sync(0xffffffffu, probe);
    const bool is_i64 = (probe == 0u);

    unsigned int id[TOK_PER_WARP];
    if (is_i64) {
        const ulonglong2* xl = (const ulonglong2*)x32;
        ulonglong2 a = __ldg(&xl[(t0 >> 1) + 0]);  // tokens t0, t0+1
        ulonglong2 b = __ldg(&xl[(t0 >> 1) + 1]);  // tokens t0+2, t0+3
        id[0] = (unsigned int)a.x; id[1] = (unsigned int)a.y;
        id[2] = (unsigned int)b.x; id[3] = (unsigned int)b.y;
    } else {
        id[0] = a32.x; id[1] = a32.y; id[2] = a32.z; id[3] = a32.w;
    }

    // ---- 4 independent 512B row gathers, L2-only caching (no L1 fill) ----
    float4 v[TOK_PER_WARP];
#pragma unroll
    for (int t = 0; t < TOK_PER_WARP; t++)
        v[t] = __ldcg(&w4[(size_t)id[t] * EMBED_V4 + lane]);

    // ---- 4 independent scale loads (overlap the gathers; L1-cached) ----
    float sc[TOK_PER_WARP];
#pragma unroll
    for (int t = 0; t < TOK_PER_WARP; t++)
        sc[t] = (id[t] == 0u) ? 0.0f : __ldg(&mask[id[t]]);

    // ---- scale + streaming store, each token as soon as it's ready ----
    float4* o = out4 + (size_t)t0 * EMBED_V4 + lane;
#pragma unroll
    for (int t = 0; t < TOK_PER_WARP; t++) {
        v[t].x *= sc[t]; v[t].y *= sc[t]; v[t].z *= sc[t]; v[t].w *= sc[t];
        __stcs(o + (size_t)t * EMBED_V4, v[t]);
    }
}

extern "C" void kernel_launch(void* const* d_in, const int* in_sizes, int n_in,
                              void* d_out, int out_size) {
    const unsigned int* x   = (const unsigned int*)d_in[0]; // [B*S] i64 or i32
    const float*        w   = (const float*)d_in[1];        // [V, 128]
    const float*        msk = (const float*)d_in[2];        // [V]
    float*              out = (float*)d_out;                // [B*S, 128]

    const int n_tokens = in_sizes[0];
    const int warps    = (n_tokens + TOK_PER_WARP - 1) / TOK_PER_WARP;
    const int blocks   = (warps * 32 + THREADS - 1) / THREADS;

    vdembed_kernel<<<blocks, THREADS>>>(
        x, (const float4*)w, msk, (float4*)out, n_tokens);
}